// round 3
// baseline (speedup 1.0000x reference)
#include <cuda_runtime.h>
#include <math.h>

#define B_ 4
#define L_ 4096
#define D_ 1024
#define R_ 16
#define PLU_ 120
#define GEO_ 256
#define BL_ 16384
#define EPS_ 1e-6f

// Scratch (static device globals: allocation-free)
__device__ float d_Z[BL_ * R_];      // (B*L, 16)
__device__ float d_S[BL_ * GEO_];    // (B*L, 256)  = (sum_delta gelu(...))/count
__device__ float d_C[BL_];           // count per token
__device__ float d_G[BL_ * D_];      // (B*L, 1024) = g

__constant__ int c_off[6] = {1, 2, 4, 8, 16, 32};

// ---------------- z = h @ red_w + red_b ----------------
__global__ void k_z(const float* __restrict__ h,
                    const float* __restrict__ rw,
                    const float* __restrict__ rb) {
    int t = blockIdx.x * 16 + (threadIdx.x >> 4);
    int r = threadIdx.x & 15;
    const float* hrow = h + (size_t)t * D_;
    float acc = rb[r];
    #pragma unroll 4
    for (int d = 0; d < D_; d += 4) {
        float4 hv = *reinterpret_cast<const float4*>(hrow + d);
        acc += hv.x * rw[(d + 0) * R_ + r];
        acc += hv.y * rw[(d + 1) * R_ + r];
        acc += hv.z * rw[(d + 2) * R_ + r];
        acc += hv.w * rw[(d + 3) * R_ + r];
    }
    d_Z[t * R_ + r] = acc;
}

__device__ __forceinline__ float gelu_exact(float x) {
    return 0.5f * x * (1.f + erff(x * 0.7071067811865476f));
}

// ---------------- geom: per-token sum over deltas of gelu(plucker @ g1_w + g1_b) ----------------
#define K2_TOK 16
__global__ void k_geom(const float* __restrict__ g1w,
                       const float* __restrict__ g1b) {
    extern __shared__ float g1sh[];       // PLU_*GEO_ floats (120 KB)
    __shared__ float psh[PLU_];
    __shared__ float s_inv;
    int tid = threadIdx.x;

    for (int i = tid; i < PLU_ * GEO_; i += 256) g1sh[i] = g1w[i];
    float bj = g1b[tid];

    // triu pair indices for this thread (k -> (i,j), i<j)
    int pi = 0, pj = 0;
    if (tid < PLU_) {
        int k = tid, i = 0, len = R_ - 1;
        while (k >= len) { k -= len; i++; len--; }
        pi = i; pj = i + 1 + k;
    }
    __syncthreads();

    int t0 = blockIdx.x * K2_TOK;
    for (int tt = 0; tt < K2_TOK; ++tt) {
        int t = t0 + tt;
        int l = t & (L_ - 1);
        float acc = 0.f;
        int cnt = 0;
        for (int di = 0; di < 6; ++di) {
            int delta = c_off[di];
            if (l < delta) continue;   // uniform over block
            cnt++;
            if (tid < PLU_) {
                const float* v = d_Z + (size_t)t * R_;
                const float* u = v - delta * R_;   // same batch guaranteed (l >= delta)
                psh[tid] = u[pi] * v[pj] - u[pj] * v[pi];
            }
            __syncthreads();
            if (tid < 32) {
                float a0 = psh[tid];
                float a1 = psh[tid + 32];
                float a2 = psh[tid + 64];
                float a3 = (tid + 96 < PLU_) ? psh[tid + 96] : 0.f;
                float sq = a0 * a0 + a1 * a1 + a2 * a2 + a3 * a3;
                #pragma unroll
                for (int o = 16; o > 0; o >>= 1) sq += __shfl_xor_sync(0xffffffffu, sq, o);
                if (tid == 0) s_inv = 1.f / fmaxf(sqrtf(sq), EPS_);
            }
            __syncthreads();
            float inv = s_inv;
            float dot = 0.f;
            #pragma unroll 8
            for (int k = 0; k < PLU_; ++k) dot += psh[k] * g1sh[k * GEO_ + tid];
            acc += gelu_exact(dot * inv + bj);
            __syncthreads();   // protect psh/s_inv before next delta
        }
        float sc = cnt > 0 ? 1.f / (float)cnt : 0.f;
        d_S[(size_t)t * GEO_ + tid] = acc * sc;
        if (tid == 0) d_C[t] = (float)cnt;
    }
}

// ---------------- tiled fp32 GEMMs ----------------
#define BM 64
#define BN 64
#define BK 16

// g = S @ g2_w + g2_b (zeroed where count==0)  -> d_G
__global__ void k_g2(const float* __restrict__ g2w,
                     const float* __restrict__ g2b) {
    __shared__ float As[BK][BM];
    __shared__ float Bs[BK][BN];
    int tid = threadIdx.x;
    int m0 = blockIdx.y * BM;
    int n0 = blockIdx.x * BN;
    int tx = tid & 15, ty = tid >> 4;
    int arow = tid >> 2, acol = (tid & 3) << 2;
    int brow = tid >> 4, bcol = (tid & 15) << 2;
    float c[4][4] = {};

    for (int k0 = 0; k0 < GEO_; k0 += BK) {
        float4 av = *reinterpret_cast<const float4*>(
            d_S + (size_t)(m0 + arow) * GEO_ + k0 + acol);
        As[acol + 0][arow] = av.x;
        As[acol + 1][arow] = av.y;
        As[acol + 2][arow] = av.z;
        As[acol + 3][arow] = av.w;
        *reinterpret_cast<float4*>(&Bs[brow][bcol]) =
            *reinterpret_cast<const float4*>(g2w + (size_t)(k0 + brow) * D_ + n0 + bcol);
        __syncthreads();
        #pragma unroll
        for (int k = 0; k < BK; ++k) {
            float4 a = *reinterpret_cast<const float4*>(&As[k][ty * 4]);
            float4 b = *reinterpret_cast<const float4*>(&Bs[k][tx * 4]);
            float ar[4] = {a.x, a.y, a.z, a.w};
            float br[4] = {b.x, b.y, b.z, b.w};
            #pragma unroll
            for (int i = 0; i < 4; ++i)
                #pragma unroll
                for (int j = 0; j < 4; ++j)
                    c[i][j] += ar[i] * br[j];
        }
        __syncthreads();
    }
    #pragma unroll
    for (int i = 0; i < 4; ++i) {
        int m = m0 + ty * 4 + i;
        float cntv = d_C[m];
        #pragma unroll
        for (int j = 0; j < 4; ++j) {
            int n = n0 + tx * 4 + j;
            d_G[(size_t)m * D_ + n] = (cntv > 0.f) ? c[i][j] + g2b[n] : 0.f;
        }
    }
}

// pre = [h|g] @ gate_w + gate_b; out = sigmoid(pre)*h + (1-sigmoid)*g
__global__ void k_gate(const float* __restrict__ h,
                       const float* __restrict__ gw,
                       const float* __restrict__ gb,
                       float* __restrict__ out) {
    __shared__ float As[BK][BM];
    __shared__ float Bs[BK][BN];
    int tid = threadIdx.x;
    int m0 = blockIdx.y * BM;
    int n0 = blockIdx.x * BN;
    int tx = tid & 15, ty = tid >> 4;
    int arow = tid >> 2, acol = (tid & 3) << 2;
    int brow = tid >> 4, bcol = (tid & 15) << 2;
    float c[4][4] = {};

    for (int k0 = 0; k0 < 2 * D_; k0 += BK) {
        const float* Ap = (k0 < D_)
            ? (h   + (size_t)(m0 + arow) * D_ + k0 + acol)
            : (d_G + (size_t)(m0 + arow) * D_ + (k0 - D_) + acol);
        float4 av = *reinterpret_cast<const float4*>(Ap);
        As[acol + 0][arow] = av.x;
        As[acol + 1][arow] = av.y;
        As[acol + 2][arow] = av.z;
        As[acol + 3][arow] = av.w;
        *reinterpret_cast<float4*>(&Bs[brow][bcol]) =
            *reinterpret_cast<const float4*>(gw + (size_t)(k0 + brow) * D_ + n0 + bcol);
        __syncthreads();
        #pragma unroll
        for (int k = 0; k < BK; ++k) {
            float4 a = *reinterpret_cast<const float4*>(&As[k][ty * 4]);
            float4 b = *reinterpret_cast<const float4*>(&Bs[k][tx * 4]);
            float ar[4] = {a.x, a.y, a.z, a.w};
            float br[4] = {b.x, b.y, b.z, b.w};
            #pragma unroll
            for (int i = 0; i < 4; ++i)
                #pragma unroll
                for (int j = 0; j < 4; ++j)
                    c[i][j] += ar[i] * br[j];
        }
        __syncthreads();
    }
    #pragma unroll
    for (int i = 0; i < 4; ++i) {
        int m = m0 + ty * 4 + i;
        float4 hv = *reinterpret_cast<const float4*>(h   + (size_t)m * D_ + n0 + tx * 4);
        float4 gv = *reinterpret_cast<const float4*>(d_G + (size_t)m * D_ + n0 + tx * 4);
        float hr[4] = {hv.x, hv.y, hv.z, hv.w};
        float gr[4] = {gv.x, gv.y, gv.z, gv.w};
        float4 o;
        float* op = &o.x;
        #pragma unroll
        for (int j = 0; j < 4; ++j) {
            int n = n0 + tx * 4 + j;
            float pre = c[i][j] + gb[n];
            float alpha = 1.f / (1.f + expf(-pre));
            op[j] = alpha * hr[j] + (1.f - alpha) * gr[j];
        }
        *reinterpret_cast<float4*>(out + (size_t)m * D_ + n0 + tx * 4) = o;
    }
}

extern "C" void kernel_launch(void* const* d_in, const int* in_sizes, int n_in,
                              void* d_out, int out_size) {
    const float* h   = (const float*)d_in[0];
    const float* rw  = (const float*)d_in[1];
    const float* rb  = (const float*)d_in[2];
    const float* g1w = (const float*)d_in[3];
    const float* g1b = (const float*)d_in[4];
    const float* g2w = (const float*)d_in[5];
    const float* g2b = (const float*)d_in[6];
    const float* gw  = (const float*)d_in[7];
    const float* gb  = (const float*)d_in[8];
    float* out = (float*)d_out;
    (void)in_sizes; (void)n_in; (void)out_size;

    cudaFuncSetAttribute(k_geom, cudaFuncAttributeMaxDynamicSharedMemorySize,
                         PLU_ * GEO_ * (int)sizeof(float));

    k_z<<<BL_ / 16, 256>>>(h, rw, rb);
    k_geom<<<BL_ / K2_TOK, 256, PLU_ * GEO_ * sizeof(float)>>>(g1w, g1b);
    dim3 gdim(D_ / BN, BL_ / BM);
    k_g2<<<gdim, 256>>>(g2w, g2b);
    k_gate<<<gdim, 256>>>(h, gw, gb, out);
}

// round 5
// speedup vs baseline: 1.3288x; 1.3288x over previous
#include <cuda_runtime.h>
#include <mma.h>
#include <math.h>
#include <stdint.h>

using namespace nvcuda;

#define B_ 4
#define L_ 4096
#define D_ 1024
#define R_ 16
#define PLU_ 120
#define GEO_ 256
#define BL_ 16384
#define EPS_ 1e-6f

// Scratch (static device globals: allocation-free)
__device__ float d_Z[BL_ * R_];      // (B*L, 16)
__device__ float d_S[BL_ * GEO_];    // (B*L, 256)  = (sum_delta gelu(...))/count
__device__ float d_C[BL_];           // count per token
__device__ float d_G[BL_ * D_];      // (B*L, 1024) = g

__constant__ int c_off[6] = {1, 2, 4, 8, 16, 32};

__device__ __forceinline__ uint32_t smem_u32(const void* p) {
    uint32_t a;
    asm("{ .reg .u64 t; cvta.to.shared.u64 t, %1; cvt.u32.u64 %0, t; }"
        : "=r"(a) : "l"(p));
    return a;
}

__device__ __forceinline__ void cp16(uint32_t s, const void* g) {
    asm volatile("cp.async.cg.shared.global [%0], [%1], 16;" :: "r"(s), "l"(g));
}
__device__ __forceinline__ void cp_commit() {
    asm volatile("cp.async.commit_group;");
}
template <int N>
__device__ __forceinline__ void cp_wait() {
    asm volatile("cp.async.wait_group %0;" :: "n"(N));
}

// ---------------- z = h @ red_w + red_b ----------------
__global__ void k_z(const float* __restrict__ h,
                    const float* __restrict__ rw,
                    const float* __restrict__ rb) {
    int t = blockIdx.x * 16 + (threadIdx.x >> 4);
    int r = threadIdx.x & 15;
    const float* hrow = h + (size_t)t * D_;
    float acc = rb[r];
    #pragma unroll 4
    for (int d = 0; d < D_; d += 4) {
        float4 hv = *reinterpret_cast<const float4*>(hrow + d);
        acc += hv.x * rw[(d + 0) * R_ + r];
        acc += hv.y * rw[(d + 1) * R_ + r];
        acc += hv.z * rw[(d + 2) * R_ + r];
        acc += hv.w * rw[(d + 3) * R_ + r];
    }
    d_Z[t * R_ + r] = acc;
}

__device__ __forceinline__ float gelu_exact(float x) {
    return 0.5f * x * (1.f + erff(x * 0.7071067811865476f));
}

// ---------------- geom: per-token sum over deltas of gelu(plucker @ g1_w + g1_b) ----------------
#define K2_TOK 16
__global__ void k_geom(const float* __restrict__ g1w,
                       const float* __restrict__ g1b) {
    extern __shared__ float g1sh[];       // PLU_*GEO_ floats (120 KB)
    __shared__ float psh[PLU_];
    __shared__ float s_inv;
    int tid = threadIdx.x;

    for (int i = tid; i < PLU_ * GEO_; i += 256) g1sh[i] = g1w[i];
    float bj = g1b[tid];

    int pi = 0, pj = 0;
    if (tid < PLU_) {
        int k = tid, i = 0, len = R_ - 1;
        while (k >= len) { k -= len; i++; len--; }
        pi = i; pj = i + 1 + k;
    }
    __syncthreads();

    int t0 = blockIdx.x * K2_TOK;
    for (int tt = 0; tt < K2_TOK; ++tt) {
        int t = t0 + tt;
        int l = t & (L_ - 1);
        float acc = 0.f;
        int cnt = 0;
        for (int di = 0; di < 6; ++di) {
            int delta = c_off[di];
            if (l < delta) continue;
            cnt++;
            if (tid < PLU_) {
                const float* v = d_Z + (size_t)t * R_;
                const float* u = v - delta * R_;
                psh[tid] = u[pi] * v[pj] - u[pj] * v[pi];
            }
            __syncthreads();
            if (tid < 32) {
                float a0 = psh[tid];
                float a1 = psh[tid + 32];
                float a2 = psh[tid + 64];
                float a3 = (tid + 96 < PLU_) ? psh[tid + 96] : 0.f;
                float sq = a0 * a0 + a1 * a1 + a2 * a2 + a3 * a3;
                #pragma unroll
                for (int o = 16; o > 0; o >>= 1) sq += __shfl_xor_sync(0xffffffffu, sq, o);
                if (tid == 0) s_inv = 1.f / fmaxf(sqrtf(sq), EPS_);
            }
            __syncthreads();
            float inv = s_inv;
            float dot = 0.f;
            #pragma unroll 8
            for (int k = 0; k < PLU_; ++k) dot += psh[k] * g1sh[k * GEO_ + tid];
            acc += gelu_exact(dot * inv + bj);
            __syncthreads();
        }
        float sc = cnt > 0 ? 1.f / (float)cnt : 0.f;
        d_S[(size_t)t * GEO_ + tid] = acc * sc;
        if (tid == 0) d_C[t] = (float)cnt;
    }
}

// ---------------- wmma tf32 GEMM: tile 128x128, BK=32, 2-stage cp.async ----------------
// MODE 0: A = d_S (K=256),  B = g2_w [256][1024];   d_G = cnt>0 ? acc+g2_b : 0
// MODE 1: A = [h|d_G] (K=2048), B = gate_w [2048][1024]; out = sig(acc+gb)*h+(1-sig)*g
#define LDA 40
#define LDB 136
#define STAGE_F 9472               // floats per stage (A:128*40=5120, B:32*136=4352)
#define SMEM_GEMM (2 * STAGE_F * 4)  // 75776 bytes

template <int MODE>
__global__ void __launch_bounds__(256) k_gemm(const float* __restrict__ hA,
                                              const float* __restrict__ Bw,
                                              const float* __restrict__ bias,
                                              float* __restrict__ out) {
    extern __shared__ __align__(128) float sm[];
    constexpr int KTOT = MODE ? 2 * D_ : GEO_;
    constexpr int NIT = KTOT / 32;

    const int tid = threadIdx.x;
    const int wid = tid >> 5, lane = tid & 31;
    const int wm = wid >> 1, wn = wid & 1;      // 4 x 2 warp grid
    const int m0 = blockIdx.y * 128;
    const int n0 = blockIdx.x * 128;
    const uint32_t smb = smem_u32(sm);

    wmma::fragment<wmma::accumulator, 16, 16, 8, float> acc[2][4];
    #pragma unroll
    for (int i = 0; i < 2; ++i)
        #pragma unroll
        for (int j = 0; j < 4; ++j) wmma::fill_fragment(acc[i][j], 0.f);

    auto load_async = [&](int it, int s) {
        const int k0 = it * 32;
        const uint32_t aoff = s * STAGE_F;
        const uint32_t boff = s * STAGE_F + 128 * LDA;
        #pragma unroll
        for (int p = 0; p < 4; ++p) {
            int idx = tid + p * 256;
            int row = idx >> 3, c4 = idx & 7;
            const float* gp;
            if (MODE)
                gp = (k0 < D_) ? hA + (size_t)(m0 + row) * D_ + k0 + c4 * 4
                               : d_G + (size_t)(m0 + row) * D_ + (k0 - D_) + c4 * 4;
            else
                gp = d_S + (size_t)(m0 + row) * GEO_ + k0 + c4 * 4;
            cp16(smb + (aoff + row * LDA + c4 * 4) * 4, gp);
        }
        #pragma unroll
        for (int p = 0; p < 4; ++p) {
            int idx = tid + p * 256;
            int row = idx >> 5, c4 = idx & 31;
            cp16(smb + (boff + row * LDB + c4 * 4) * 4,
                 Bw + (size_t)(k0 + row) * D_ + n0 + c4 * 4);
        }
        cp_commit();
    };

    auto compute = [&](int s) {
        const float* As = sm + s * STAGE_F;
        const float* Bs = sm + s * STAGE_F + 128 * LDA;
        #pragma unroll
        for (int ks = 0; ks < 4; ++ks) {
            wmma::fragment<wmma::matrix_a, 16, 16, 8, wmma::precision::tf32,
                           wmma::row_major> a[2];
            wmma::fragment<wmma::matrix_b, 16, 16, 8, wmma::precision::tf32,
                           wmma::row_major> b[4];
            #pragma unroll
            for (int i = 0; i < 2; ++i) {
                wmma::load_matrix_sync(a[i], As + (wm * 32 + i * 16) * LDA + ks * 8, LDA);
                #pragma unroll
                for (int e = 0; e < a[i].num_elements; ++e)
                    a[i].x[e] = wmma::__float_to_tf32(a[i].x[e]);
            }
            #pragma unroll
            for (int j = 0; j < 4; ++j) {
                wmma::load_matrix_sync(b[j], Bs + ks * 8 * LDB + wn * 64 + j * 16, LDB);
                #pragma unroll
                for (int e = 0; e < b[j].num_elements; ++e)
                    b[j].x[e] = wmma::__float_to_tf32(b[j].x[e]);
            }
            #pragma unroll
            for (int i = 0; i < 2; ++i)
                #pragma unroll
                for (int j = 0; j < 4; ++j)
                    wmma::mma_sync(acc[i][j], a[i], b[j], acc[i][j]);
        }
    };

    load_async(0, 0);
    for (int it = 0; it < NIT; ++it) {
        int cur = it & 1;
        if (it + 1 < NIT) {
            load_async(it + 1, 1 - cur);
            cp_wait<1>();
        } else {
            cp_wait<0>();
        }
        __syncthreads();
        compute(cur);
        __syncthreads();
    }

    // Epilogue: spill accumulators to smem (safe: all compute done), apply fused op.
    float* ep = sm + wid * 2048;   // 32 x 64 per warp
    #pragma unroll
    for (int i = 0; i < 2; ++i)
        #pragma unroll
        for (int j = 0; j < 4; ++j)
            wmma::store_matrix_sync(ep + i * 16 * 64 + j * 16, acc[i][j], 64,
                                    wmma::mem_row_major);
    __syncwarp();

    const int m = m0 + wm * 32 + lane;
    const float* row = ep + lane * 64;
    const int nbase = n0 + wn * 64;
    if (MODE) {
        const float* hp = hA + (size_t)m * D_ + nbase;
        const float* gp = d_G + (size_t)m * D_ + nbase;
        float* op = out + (size_t)m * D_ + nbase;
        #pragma unroll
        for (int c4 = 0; c4 < 16; ++c4) {
            float4 v = *reinterpret_cast<const float4*>(row + c4 * 4);
            float4 bb = *reinterpret_cast<const float4*>(bias + nbase + c4 * 4);
            float4 hv = *reinterpret_cast<const float4*>(hp + c4 * 4);
            float4 gv = *reinterpret_cast<const float4*>(gp + c4 * 4);
            float pr[4] = {v.x + bb.x, v.y + bb.y, v.z + bb.z, v.w + bb.w};
            float hr[4] = {hv.x, hv.y, hv.z, hv.w};
            float gr[4] = {gv.x, gv.y, gv.z, gv.w};
            float4 o;
            float* opv = &o.x;
            #pragma unroll
            for (int j = 0; j < 4; ++j) {
                float alpha = 1.f / (1.f + expf(-pr[j]));
                opv[j] = alpha * hr[j] + (1.f - alpha) * gr[j];
            }
            *reinterpret_cast<float4*>(op + c4 * 4) = o;
        }
    } else {
        float cnt = d_C[m];
        float* gp = d_G + (size_t)m * D_ + nbase;
        #pragma unroll
        for (int c4 = 0; c4 < 16; ++c4) {
            float4 v = *reinterpret_cast<const float4*>(row + c4 * 4);
            float4 bb = *reinterpret_cast<const float4*>(bias + nbase + c4 * 4);
            float4 o;
            o.x = (cnt > 0.f) ? v.x + bb.x : 0.f;
            o.y = (cnt > 0.f) ? v.y + bb.y : 0.f;
            o.z = (cnt > 0.f) ? v.z + bb.z : 0.f;
            o.w = (cnt > 0.f) ? v.w + bb.w : 0.f;
            *reinterpret_cast<float4*>(gp + c4 * 4) = o;
        }
    }
}

extern "C" void kernel_launch(void* const* d_in, const int* in_sizes, int n_in,
                              void* d_out, int out_size) {
    const float* h   = (const float*)d_in[0];
    const float* rw  = (const float*)d_in[1];
    const float* rb  = (const float*)d_in[2];
    const float* g1w = (const float*)d_in[3];
    const float* g1b = (const float*)d_in[4];
    const float* g2w = (const float*)d_in[5];
    const float* g2b = (const float*)d_in[6];
    const float* gw  = (const float*)d_in[7];
    const float* gb  = (const float*)d_in[8];
    float* out = (float*)d_out;
    (void)in_sizes; (void)n_in; (void)out_size;

    cudaFuncSetAttribute(k_geom, cudaFuncAttributeMaxDynamicSharedMemorySize,
                         PLU_ * GEO_ * (int)sizeof(float));
    cudaFuncSetAttribute(k_gemm<0>, cudaFuncAttributeMaxDynamicSharedMemorySize, SMEM_GEMM);
    cudaFuncSetAttribute(k_gemm<1>, cudaFuncAttributeMaxDynamicSharedMemorySize, SMEM_GEMM);

    k_z<<<BL_ / 16, 256>>>(h, rw, rb);
    k_geom<<<BL_ / K2_TOK, 256, PLU_ * GEO_ * sizeof(float)>>>(g1w, g1b);

    dim3 gdim(D_ / 128, BL_ / 128);   // (8, 128)
    k_gemm<0><<<gdim, 256, SMEM_GEMM>>>(nullptr, g2w, g2b, nullptr);
    k_gemm<1><<<gdim, 256, SMEM_GEMM>>>(h, gw, gb, out);
}

// round 8
// speedup vs baseline: 2.2857x; 1.7200x over previous
#include <cuda_runtime.h>
#include <mma.h>
#include <math.h>
#include <stdint.h>

using namespace nvcuda;

#define B_ 4
#define L_ 4096
#define D_ 1024
#define R_ 16
#define PLU_ 120
#define PLUP_ 128
#define GEO_ 256
#define BL_ 16384
#define MROWS_ (6 * BL_)
#define EPS_ 1e-6f

// Scratch (static device globals: allocation-free)
__device__ float d_Z[BL_ * R_];                    // (B*L, 16)
__device__ float d_S[BL_ * GEO_];                  // (B*L, 256) tf32-rounded
__device__ float d_P[(size_t)MROWS_ * PLUP_];      // plucker rows, tf32-rounded
__device__ float d_U[(size_t)MROWS_ * GEO_];       // gelu(P@g1w+b)
__device__ float d_HG[(size_t)BL_ * 2 * D_];       // [h | g], tf32-rounded (GEMM A)
__device__ float d_G[(size_t)BL_ * D_];            // raw fp32 g (epilogue blend)
__device__ float d_W2c[GEO_ * D_];                 // cvt g2_w
__device__ float d_Wgc[2 * D_ * D_];               // cvt gate_w
__device__ float d_G1c[PLUP_ * GEO_];              // cvt g1_w (rows 120..127 = 0)

__constant__ int c_off[6] = {1, 2, 4, 8, 16, 32};

__device__ __forceinline__ uint32_t smem_u32(const void* p) {
    uint32_t a;
    asm("{ .reg .u64 t; cvta.to.shared.u64 t, %1; cvt.u32.u64 %0, t; }"
        : "=r"(a) : "l"(p));
    return a;
}
__device__ __forceinline__ void cp16(uint32_t s, const void* g) {
    asm volatile("cp.async.cg.shared.global [%0], [%1], 16;" :: "r"(s), "l"(g));
}
__device__ __forceinline__ void cp_commit() { asm volatile("cp.async.commit_group;"); }
template <int N>
__device__ __forceinline__ void cp_wait() {
    asm volatile("cp.async.wait_group %0;" :: "n"(N));
}
__device__ __forceinline__ float to_tf32(float x) {
    float r;
    asm("cvt.rna.tf32.f32 %0, %1;" : "=f"(r) : "f"(x));
    return r;
}
__device__ __forceinline__ float4 cvt4(float4 v) {
    v.x = to_tf32(v.x); v.y = to_tf32(v.y); v.z = to_tf32(v.z); v.w = to_tf32(v.w);
    return v;
}
__device__ __forceinline__ float gelu_exact(float x) {
    return 0.5f * x * (1.f + erff(x * 0.7071067811865476f));
}
__device__ __forceinline__ int count_of(int l) {
    return (l >= 1) + (l >= 2) + (l >= 4) + (l >= 8) + (l >= 16) + (l >= 32);
}

// ---------------- z = h @ red_w + red_b ----------------
__global__ void k_z(const float* __restrict__ h,
                    const float* __restrict__ rw,
                    const float* __restrict__ rb) {
    int t = blockIdx.x * 16 + (threadIdx.x >> 4);
    int r = threadIdx.x & 15;
    const float* hrow = h + (size_t)t * D_;
    float acc = rb[r];
    #pragma unroll 4
    for (int d = 0; d < D_; d += 4) {
        float4 hv = *reinterpret_cast<const float4*>(hrow + d);
        acc += hv.x * rw[(d + 0) * R_ + r];
        acc += hv.y * rw[(d + 1) * R_ + r];
        acc += hv.z * rw[(d + 2) * R_ + r];
        acc += hv.w * rw[(d + 3) * R_ + r];
    }
    d_Z[t * R_ + r] = acc;
}

// ---------------- cvt copies ----------------
__global__ void k_cvt_h(const float* __restrict__ h) {   // h -> d_HG[:, 0:1024]
    int row = blockIdx.x;
    int c = threadIdx.x * 4;
    float4 v = cvt4(*reinterpret_cast<const float4*>(h + (size_t)row * D_ + c));
    *reinterpret_cast<float4*>(d_HG + (size_t)row * 2 * D_ + c) = v;
}
__global__ void k_cvt_w(const float* __restrict__ src, float* __restrict__ dst) {
    size_t i = ((size_t)blockIdx.x * 256 + threadIdx.x) * 4;
    *reinterpret_cast<float4*>(dst + i) =
        cvt4(*reinterpret_cast<const float4*>(src + i));
}
__global__ void k_cvt_g1(const float* __restrict__ g1w) {  // pad 120->128 rows
    int fid = blockIdx.x * 256 + threadIdx.x;      // 8192 float4s
    int row = fid >> 6;
    int c = (fid & 63) * 4;
    float4 v = make_float4(0.f, 0.f, 0.f, 0.f);
    if (row < PLU_)
        v = cvt4(*reinterpret_cast<const float4*>(g1w + (size_t)row * GEO_ + c));
    *reinterpret_cast<float4*>(d_G1c + (size_t)row * GEO_ + c) = v;
}

// ---------------- plucker rows: d_P[di*BL + t][0:128] ----------------
// NOTE: all shuffles are warp-uniform (no divergent __shfl_sync).
__global__ void k_plucker() {
    int wid = threadIdx.x >> 5, lane = threadIdx.x & 31;
    int ridx = blockIdx.x * 8 + wid;
    int di = ridx / BL_;
    int t = ridx - di * BL_;
    int l = t & (L_ - 1);
    int delta = c_off[di];
    float* dst = d_P + (size_t)ridx * PLUP_;
    if (l < delta) {                       // warp-uniform branch
        #pragma unroll
        for (int q = 0; q < 4; ++q) dst[lane + q * 32] = 0.f;
        return;
    }
    int tp = t - delta;
    float w = (lane < 16) ? d_Z[tp * R_ + lane] : d_Z[t * R_ + lane - 16];
    float p[4];
    float sq = 0.f;
    #pragma unroll
    for (int q = 0; q < 4; ++q) {
        int k = lane + q * 32;
        int kc = (k < PLU_) ? k : 0;       // clamp decode; select 0 afterwards
        int kk = kc, i = 0, len = R_ - 1;
        while (kk >= len) { kk -= len; i++; len--; }
        int j = i + 1 + kk;
        // ALL 32 lanes execute these shuffles
        float ui = __shfl_sync(0xffffffffu, w, i);
        float uj = __shfl_sync(0xffffffffu, w, j);
        float vi = __shfl_sync(0xffffffffu, w, 16 + i);
        float vj = __shfl_sync(0xffffffffu, w, 16 + j);
        float val = (k < PLU_) ? (ui * vj - uj * vi) : 0.f;
        p[q] = val;
        sq += val * val;
    }
    #pragma unroll
    for (int o = 16; o > 0; o >>= 1) sq += __shfl_xor_sync(0xffffffffu, sq, o);
    float inv = 1.f / fmaxf(sqrtf(sq), EPS_);
    #pragma unroll
    for (int q = 0; q < 4; ++q) dst[lane + q * 32] = to_tf32(p[q] * inv);
}

// ---------------- reduce: d_S = (sum masked d_U slices)/cnt ----------------
__global__ void k_reduce() {
    int fid = blockIdx.x * 256 + threadIdx.x;   // BL*GEO/4 float4s
    int t = fid >> 6;
    int c = (fid & 63) * 4;
    int l = t & (L_ - 1);
    float4 s = make_float4(0.f, 0.f, 0.f, 0.f);
    #pragma unroll
    for (int di = 0; di < 6; ++di) {
        if (l >= c_off[di]) {
            float4 u = *reinterpret_cast<const float4*>(
                d_U + (size_t)(di * BL_ + t) * GEO_ + c);
            s.x += u.x; s.y += u.y; s.z += u.z; s.w += u.w;
        }
    }
    int cnt = count_of(l);
    float sc = cnt > 0 ? 1.f / (float)cnt : 0.f;
    s.x = to_tf32(s.x * sc); s.y = to_tf32(s.y * sc);
    s.z = to_tf32(s.z * sc); s.w = to_tf32(s.w * sc);
    *reinterpret_cast<float4*>(d_S + (size_t)t * GEO_ + c) = s;
}

// ---------------- wmma tf32 GEMM, 128x128 tile, BK=32, 3-stage cp.async ----------------
// MODE 0: A=d_S  (K=256),  B=d_W2c: d_G raw, d_HG[:,1024+] cvt (both cnt-gated)
// MODE 1: A=d_HG (K=2048), B=d_Wgc: out = sig(acc+gb)*h + (1-sig)*d_G
// MODE 2: A=d_P  (K=128),  B=d_G1c, NG=256: d_U = gelu(acc+g1b)
#define LDA 40
#define LDB 136
#define STAGE_F 9472
#define SMEM_GEMM (3 * STAGE_F * 4)   // 113664 bytes

template <int MODE>
__global__ void __launch_bounds__(256) k_gemm(const float* __restrict__ Aw,
                                              const float* __restrict__ Bw,
                                              const float* __restrict__ bias,
                                              const float* __restrict__ hOrig,
                                              float* __restrict__ out) {
    extern __shared__ __align__(128) float sm[];
    constexpr int KTOT = (MODE == 1) ? 2 * D_ : (MODE == 0 ? GEO_ : PLUP_);
    constexpr int NG = (MODE == 2) ? GEO_ : D_;
    constexpr int NIT = KTOT / 32;

    const int tid = threadIdx.x;
    const int wid = tid >> 5, lane = tid & 31;
    const int wm = wid >> 1, wn = wid & 1;
    const int m0 = blockIdx.y * 128;
    const int n0 = blockIdx.x * 128;
    const uint32_t smb = smem_u32(sm);

    wmma::fragment<wmma::accumulator, 16, 16, 8, float> acc[2][4];
    #pragma unroll
    for (int i = 0; i < 2; ++i)
        #pragma unroll
        for (int j = 0; j < 4; ++j) wmma::fill_fragment(acc[i][j], 0.f);

    auto load_async = [&](int it, int s) {
        const int k0 = it * 32;
        const uint32_t aoff = s * STAGE_F;
        const uint32_t boff = s * STAGE_F + 128 * LDA;
        #pragma unroll
        for (int p = 0; p < 4; ++p) {
            int idx = tid + p * 256;
            int row = idx >> 3, c4 = idx & 7;
            cp16(smb + (aoff + row * LDA + c4 * 4) * 4,
                 Aw + (size_t)(m0 + row) * KTOT + k0 + c4 * 4);
        }
        #pragma unroll
        for (int p = 0; p < 4; ++p) {
            int idx = tid + p * 256;
            int row = idx >> 5, c4 = idx & 31;
            cp16(smb + (boff + row * LDB + c4 * 4) * 4,
                 Bw + (size_t)(k0 + row) * NG + n0 + c4 * 4);
        }
        cp_commit();
    };

    auto compute = [&](int s) {
        const float* As = sm + s * STAGE_F;
        const float* Bs = sm + s * STAGE_F + 128 * LDA;
        #pragma unroll
        for (int ks = 0; ks < 4; ++ks) {
            wmma::fragment<wmma::matrix_a, 16, 16, 8, wmma::precision::tf32,
                           wmma::row_major> a[2];
            wmma::fragment<wmma::matrix_b, 16, 16, 8, wmma::precision::tf32,
                           wmma::row_major> b[4];
            #pragma unroll
            for (int i = 0; i < 2; ++i)
                wmma::load_matrix_sync(a[i], As + (wm * 32 + i * 16) * LDA + ks * 8, LDA);
            #pragma unroll
            for (int j = 0; j < 4; ++j)
                wmma::load_matrix_sync(b[j], Bs + ks * 8 * LDB + wn * 64 + j * 16, LDB);
            #pragma unroll
            for (int i = 0; i < 2; ++i)
                #pragma unroll
                for (int j = 0; j < 4; ++j)
                    wmma::mma_sync(acc[i][j], a[i], b[j], acc[i][j]);
        }
    };

    load_async(0, 0);
    load_async(1, 1);
    for (int it = 0; it < NIT; ++it) {
        if (it == NIT - 1) cp_wait<0>();   // last tile: drain ALL groups
        else               cp_wait<1>();
        __syncthreads();
        compute(it % 3);
        if (it + 2 < NIT) load_async(it + 2, (it + 2) % 3);
    }
    __syncthreads();

    // Epilogue via smem staging
    float* ep = sm + wid * 2048;   // 32 rows x 64 cols per warp
    #pragma unroll
    for (int i = 0; i < 2; ++i)
        #pragma unroll
        for (int j = 0; j < 4; ++j)
            wmma::store_matrix_sync(ep + i * 16 * 64 + j * 16, acc[i][j], 64,
                                    wmma::mem_row_major);
    __syncwarp();

    const int m = m0 + wm * 32 + lane;
    const float* row = ep + lane * 64;
    const int nbase = n0 + wn * 64;

    if (MODE == 1) {
        const float* hp = hOrig + (size_t)m * D_ + nbase;
        const float* gp = d_G + (size_t)m * D_ + nbase;   // raw fp32 g
        float* op = out + (size_t)m * D_ + nbase;
        #pragma unroll
        for (int c4 = 0; c4 < 16; ++c4) {
            float4 v = *reinterpret_cast<const float4*>(row + c4 * 4);
            float4 bb = *reinterpret_cast<const float4*>(bias + nbase + c4 * 4);
            float4 hv = *reinterpret_cast<const float4*>(hp + c4 * 4);
            float4 gv = *reinterpret_cast<const float4*>(gp + c4 * 4);
            float pr[4] = {v.x + bb.x, v.y + bb.y, v.z + bb.z, v.w + bb.w};
            float hr[4] = {hv.x, hv.y, hv.z, hv.w};
            float gr[4] = {gv.x, gv.y, gv.z, gv.w};
            float4 o;
            float* opv = &o.x;
            #pragma unroll
            for (int j = 0; j < 4; ++j) {
                float alpha = 1.f / (1.f + expf(-pr[j]));
                opv[j] = alpha * hr[j] + (1.f - alpha) * gr[j];
            }
            *reinterpret_cast<float4*>(op + c4 * 4) = o;
        }
    } else if (MODE == 0) {
        int l = m & (L_ - 1);
        bool on = count_of(l) > 0;
        float* gp = d_G + (size_t)m * D_ + nbase;                   // raw
        float* ap = d_HG + (size_t)m * 2 * D_ + D_ + nbase;         // cvt (GEMM A)
        #pragma unroll
        for (int c4 = 0; c4 < 16; ++c4) {
            float4 v = *reinterpret_cast<const float4*>(row + c4 * 4);
            float4 bb = *reinterpret_cast<const float4*>(bias + nbase + c4 * 4);
            float4 g4, a4;
            g4.x = on ? v.x + bb.x : 0.f;
            g4.y = on ? v.y + bb.y : 0.f;
            g4.z = on ? v.z + bb.z : 0.f;
            g4.w = on ? v.w + bb.w : 0.f;
            a4.x = to_tf32(g4.x); a4.y = to_tf32(g4.y);
            a4.z = to_tf32(g4.z); a4.w = to_tf32(g4.w);
            *reinterpret_cast<float4*>(gp + c4 * 4) = g4;
            *reinterpret_cast<float4*>(ap + c4 * 4) = a4;
        }
    } else {
        float* up = out + (size_t)m * GEO_ + nbase;
        #pragma unroll
        for (int c4 = 0; c4 < 16; ++c4) {
            float4 v = *reinterpret_cast<const float4*>(row + c4 * 4);
            float4 bb = *reinterpret_cast<const float4*>(bias + nbase + c4 * 4);
            float4 o;
            o.x = gelu_exact(v.x + bb.x);
            o.y = gelu_exact(v.y + bb.y);
            o.z = gelu_exact(v.z + bb.z);
            o.w = gelu_exact(v.w + bb.w);
            *reinterpret_cast<float4*>(up + c4 * 4) = o;
        }
    }
}

extern "C" void kernel_launch(void* const* d_in, const int* in_sizes, int n_in,
                              void* d_out, int out_size) {
    const float* h   = (const float*)d_in[0];
    const float* rw  = (const float*)d_in[1];
    const float* rb  = (const float*)d_in[2];
    const float* g1w = (const float*)d_in[3];
    const float* g1b = (const float*)d_in[4];
    const float* g2w = (const float*)d_in[5];
    const float* g2b = (const float*)d_in[6];
    const float* gw  = (const float*)d_in[7];
    const float* gb  = (const float*)d_in[8];
    float* out = (float*)d_out;
    (void)in_sizes; (void)n_in; (void)out_size;

    cudaFuncSetAttribute(k_gemm<0>, cudaFuncAttributeMaxDynamicSharedMemorySize, SMEM_GEMM);
    cudaFuncSetAttribute(k_gemm<1>, cudaFuncAttributeMaxDynamicSharedMemorySize, SMEM_GEMM);
    cudaFuncSetAttribute(k_gemm<2>, cudaFuncAttributeMaxDynamicSharedMemorySize, SMEM_GEMM);

    float *pP, *pU, *pHG, *pW2, *pWg, *pG1, *pS;
    cudaGetSymbolAddress((void**)&pP, d_P);
    cudaGetSymbolAddress((void**)&pU, d_U);
    cudaGetSymbolAddress((void**)&pHG, d_HG);
    cudaGetSymbolAddress((void**)&pW2, d_W2c);
    cudaGetSymbolAddress((void**)&pWg, d_Wgc);
    cudaGetSymbolAddress((void**)&pG1, d_G1c);
    cudaGetSymbolAddress((void**)&pS, d_S);

    // prep: conversions + z
    k_cvt_w<<<GEO_ * D_ / 1024, 256>>>(g2w, pW2);
    k_cvt_w<<<2 * D_ * D_ / 1024, 256>>>(gw, pWg);
    k_cvt_g1<<<PLUP_ * GEO_ / 1024, 256>>>(g1w);
    k_cvt_h<<<BL_, 256>>>(h);
    k_z<<<BL_ / 16, 256>>>(h, rw, rb);

    // geometry path
    k_plucker<<<MROWS_ / 8, 256>>>();
    k_gemm<2><<<dim3(GEO_ / 128, MROWS_ / 128), 256, SMEM_GEMM>>>(
        pP, pG1, g1b, nullptr, pU);
    k_reduce<<<BL_ * GEO_ / 1024, 256>>>();

    // g = S @ g2_w + b  (raw into d_G, cvt into d_HG right half)
    k_gemm<0><<<dim3(D_ / 128, BL_ / 128), 256, SMEM_GEMM>>>(
        pS, pW2, g2b, nullptr, nullptr);

    // gated output
    k_gemm<1><<<dim3(D_ / 128, BL_ / 128), 256, SMEM_GEMM>>>(
        pHG, pWg, gb, h, out);
}

// round 9
// speedup vs baseline: 2.3405x; 1.0240x over previous
#include <cuda_runtime.h>
#include <mma.h>
#include <math.h>
#include <stdint.h>

using namespace nvcuda;

#define B_ 4
#define L_ 4096
#define D_ 1024
#define R_ 16
#define PLU_ 120
#define PLUP_ 128
#define GEO_ 256
#define BL_ 16384
#define MROWS_ (6 * BL_)
#define EPS_ 1e-6f

// Scratch (static device globals: allocation-free)
__device__ float d_Z[BL_ * R_];                  // (B*L, 16)
__device__ float d_S[BL_ * GEO_];                // (B*L, 256)
__device__ float d_P[(size_t)MROWS_ * PLUP_];    // plucker rows (cols 120..127 = 0)
__device__ float d_U[(size_t)MROWS_ * GEO_];     // gelu(P@g1w+b)
__device__ float d_G[(size_t)BL_ * D_];          // g (raw fp32)
__device__ float d_G1p[PLUP_ * GEO_];            // g1_w padded to 128 rows

__constant__ int c_off[6] = {1, 2, 4, 8, 16, 32};

__device__ __forceinline__ uint32_t smem_u32(const void* p) {
    uint32_t a;
    asm("{ .reg .u64 t; cvta.to.shared.u64 t, %1; cvt.u32.u64 %0, t; }"
        : "=r"(a) : "l"(p));
    return a;
}
__device__ __forceinline__ void cp16(uint32_t s, const void* g) {
    asm volatile("cp.async.cg.shared.global [%0], [%1], 16;" :: "r"(s), "l"(g));
}
__device__ __forceinline__ void cp_commit() { asm volatile("cp.async.commit_group;"); }
template <int N>
__device__ __forceinline__ void cp_wait() {
    asm volatile("cp.async.wait_group %0;" :: "n"(N));
}
__device__ __forceinline__ float gelu_exact(float x) {
    return 0.5f * x * (1.f + erff(x * 0.7071067811865476f));
}
__device__ __forceinline__ int count_of(int l) {
    return (l >= 1) + (l >= 2) + (l >= 4) + (l >= 8) + (l >= 16) + (l >= 32);
}

// ---------------- z = h @ red_w + red_b ----------------
__global__ void k_z(const float* __restrict__ h,
                    const float* __restrict__ rw,
                    const float* __restrict__ rb) {
    int t = blockIdx.x * 16 + (threadIdx.x >> 4);
    int r = threadIdx.x & 15;
    const float* hrow = h + (size_t)t * D_;
    float acc = rb[r];
    #pragma unroll 4
    for (int d = 0; d < D_; d += 4) {
        float4 hv = *reinterpret_cast<const float4*>(hrow + d);
        acc += hv.x * rw[(d + 0) * R_ + r];
        acc += hv.y * rw[(d + 1) * R_ + r];
        acc += hv.z * rw[(d + 2) * R_ + r];
        acc += hv.w * rw[(d + 3) * R_ + r];
    }
    d_Z[t * R_ + r] = acc;
}

// ---------------- pad g1_w 120 -> 128 rows (avoid OOB reads in GEMM B-loads) ----
__global__ void k_pad_g1(const float* __restrict__ g1w) {
    int fid = blockIdx.x * 256 + threadIdx.x;   // 8192 float4s
    int row = fid >> 6;
    int c = (fid & 63) * 4;
    float4 v = make_float4(0.f, 0.f, 0.f, 0.f);
    if (row < PLU_)
        v = *reinterpret_cast<const float4*>(g1w + (size_t)row * GEO_ + c);
    *reinterpret_cast<float4*>(d_G1p + (size_t)row * GEO_ + c) = v;
}

// ---------------- plucker rows: d_P[di*BL + t][0:128] ----------------
// All shuffles warp-uniform (divergence bug fixed in R8 — keep it that way).
__global__ void k_plucker() {
    int wid = threadIdx.x >> 5, lane = threadIdx.x & 31;
    int ridx = blockIdx.x * 8 + wid;
    int di = ridx / BL_;
    int t = ridx - di * BL_;
    int l = t & (L_ - 1);
    int delta = c_off[di];
    float* dst = d_P + (size_t)ridx * PLUP_;
    if (l < delta) {                       // warp-uniform branch
        #pragma unroll
        for (int q = 0; q < 4; ++q) dst[lane + q * 32] = 0.f;
        return;
    }
    int tp = t - delta;
    float w = (lane < 16) ? d_Z[tp * R_ + lane] : d_Z[t * R_ + lane - 16];
    float p[4];
    float sq = 0.f;
    #pragma unroll
    for (int q = 0; q < 4; ++q) {
        int k = lane + q * 32;
        int kc = (k < PLU_) ? k : 0;
        int kk = kc, i = 0, len = R_ - 1;
        while (kk >= len) { kk -= len; i++; len--; }
        int j = i + 1 + kk;
        float ui = __shfl_sync(0xffffffffu, w, i);
        float uj = __shfl_sync(0xffffffffu, w, j);
        float vi = __shfl_sync(0xffffffffu, w, 16 + i);
        float vj = __shfl_sync(0xffffffffu, w, 16 + j);
        float val = (k < PLU_) ? (ui * vj - uj * vi) : 0.f;
        p[q] = val;
        sq += val * val;
    }
    #pragma unroll
    for (int o = 16; o > 0; o >>= 1) sq += __shfl_xor_sync(0xffffffffu, sq, o);
    float inv = 1.f / fmaxf(sqrtf(sq), EPS_);
    #pragma unroll
    for (int q = 0; q < 4; ++q) dst[lane + q * 32] = p[q] * inv;
}

// ---------------- reduce: d_S = (sum masked d_U slices)/cnt ----------------
__global__ void k_reduce() {
    int fid = blockIdx.x * 256 + threadIdx.x;   // BL*GEO/4 float4s
    int t = fid >> 6;
    int c = (fid & 63) * 4;
    int l = t & (L_ - 1);
    float4 s = make_float4(0.f, 0.f, 0.f, 0.f);
    #pragma unroll
    for (int di = 0; di < 6; ++di) {
        if (l >= c_off[di]) {
            float4 u = *reinterpret_cast<const float4*>(
                d_U + (size_t)(di * BL_ + t) * GEO_ + c);
            s.x += u.x; s.y += u.y; s.z += u.z; s.w += u.w;
        }
    }
    int cnt = count_of(l);
    float sc = cnt > 0 ? 1.f / (float)cnt : 0.f;
    s.x *= sc; s.y *= sc; s.z *= sc; s.w *= sc;
    *reinterpret_cast<float4*>(d_S + (size_t)t * GEO_ + c) = s;
}

// ---------------- wmma tf32 GEMM, 128x128 tile, BK=64, 2-stage cp.async ----------
// HW truncates fp32 -> tf32 inside HMMA; no explicit cvt needed.
// MODE 0: A=d_S (K=256),  B=g2_w:   d_G = cnt>0 ? acc + g2b : 0
// MODE 1: A=[h|d_G] (K=2048), B=gate_w: out = sig(acc+gb)*h + (1-sig)*d_G
// MODE 2: A=d_P (K=128),  B=d_G1p (NG=256): d_U = gelu(acc + g1b)
#define LDA 72
#define LDB 136
#define STAGE_F (128 * LDA + 64 * LDB)     // 9216 + 8704 = 17920 floats
#define SMEM_GEMM (2 * STAGE_F * 4)        // 143360 bytes

template <int MODE>
__global__ void __launch_bounds__(256) k_gemm(const float* __restrict__ hA,
                                              const float* __restrict__ Bw,
                                              const float* __restrict__ bias,
                                              float* __restrict__ out) {
    extern __shared__ __align__(128) float sm[];
    constexpr int KTOT = (MODE == 1) ? 2 * D_ : (MODE == 0 ? GEO_ : PLUP_);
    constexpr int NG = (MODE == 2) ? GEO_ : D_;
    constexpr int NIT = KTOT / 64;

    const int tid = threadIdx.x;
    const int wid = tid >> 5, lane = tid & 31;
    const int wm = wid >> 1, wn = wid & 1;
    const int m0 = blockIdx.y * 128;
    const int n0 = blockIdx.x * 128;
    const uint32_t smb = smem_u32(sm);

    wmma::fragment<wmma::accumulator, 16, 16, 8, float> acc[2][4];
    #pragma unroll
    for (int i = 0; i < 2; ++i)
        #pragma unroll
        for (int j = 0; j < 4; ++j) wmma::fill_fragment(acc[i][j], 0.f);

    auto load_async = [&](int it, int s) {
        const int k0 = it * 64;
        const uint32_t aoff = s * STAGE_F;
        const uint32_t boff = s * STAGE_F + 128 * LDA;
        // A: 128 rows x 64 floats -> 2048 float4, 8 per thread
        #pragma unroll
        for (int p = 0; p < 8; ++p) {
            int idx = tid + p * 256;
            int row = idx >> 4, c4 = idx & 15;
            const float* gp;
            if (MODE == 1)
                gp = (k0 < D_) ? hA + (size_t)(m0 + row) * D_ + k0 + c4 * 4
                               : d_G + (size_t)(m0 + row) * D_ + (k0 - D_) + c4 * 4;
            else if (MODE == 0)
                gp = d_S + (size_t)(m0 + row) * GEO_ + k0 + c4 * 4;
            else
                gp = d_P + (size_t)(m0 + row) * PLUP_ + k0 + c4 * 4;
            cp16(smb + (aoff + row * LDA + c4 * 4) * 4, gp);
        }
        // B: 64 rows x 128 floats -> 2048 float4, 8 per thread
        #pragma unroll
        for (int p = 0; p < 8; ++p) {
            int idx = tid + p * 256;
            int row = idx >> 5, c4 = idx & 31;
            cp16(smb + (boff + row * LDB + c4 * 4) * 4,
                 Bw + (size_t)(k0 + row) * NG + n0 + c4 * 4);
        }
        cp_commit();
    };

    auto compute = [&](int s) {
        const float* As = sm + s * STAGE_F;
        const float* Bs = sm + s * STAGE_F + 128 * LDA;
        #pragma unroll
        for (int ks = 0; ks < 8; ++ks) {
            wmma::fragment<wmma::matrix_a, 16, 16, 8, wmma::precision::tf32,
                           wmma::row_major> a[2];
            wmma::fragment<wmma::matrix_b, 16, 16, 8, wmma::precision::tf32,
                           wmma::row_major> b[4];
            #pragma unroll
            for (int i = 0; i < 2; ++i)
                wmma::load_matrix_sync(a[i], As + (wm * 32 + i * 16) * LDA + ks * 8, LDA);
            #pragma unroll
            for (int j = 0; j < 4; ++j)
                wmma::load_matrix_sync(b[j], Bs + ks * 8 * LDB + wn * 64 + j * 16, LDB);
            #pragma unroll
            for (int i = 0; i < 2; ++i)
                #pragma unroll
                for (int j = 0; j < 4; ++j)
                    wmma::mma_sync(acc[i][j], a[i], b[j], acc[i][j]);
        }
    };

    load_async(0, 0);
    for (int it = 0; it < NIT; ++it) {
        int cur = it & 1;
        if (it + 1 < NIT) {
            load_async(it + 1, 1 - cur);
            cp_wait<1>();
        } else {
            cp_wait<0>();
        }
        __syncthreads();
        compute(cur);
        __syncthreads();
    }

    // Epilogue via smem staging
    float* ep = sm + wid * 2048;   // 32 rows x 64 cols per warp
    #pragma unroll
    for (int i = 0; i < 2; ++i)
        #pragma unroll
        for (int j = 0; j < 4; ++j)
            wmma::store_matrix_sync(ep + i * 16 * 64 + j * 16, acc[i][j], 64,
                                    wmma::mem_row_major);
    __syncwarp();

    const int m = m0 + wm * 32 + lane;
    const float* row = ep + lane * 64;
    const int nbase = n0 + wn * 64;

    if (MODE == 1) {
        const float* hp = hA + (size_t)m * D_ + nbase;
        const float* gp = d_G + (size_t)m * D_ + nbase;
        float* op = out + (size_t)m * D_ + nbase;
        #pragma unroll
        for (int c4 = 0; c4 < 16; ++c4) {
            float4 v = *reinterpret_cast<const float4*>(row + c4 * 4);
            float4 bb = *reinterpret_cast<const float4*>(bias + nbase + c4 * 4);
            float4 hv = *reinterpret_cast<const float4*>(hp + c4 * 4);
            float4 gv = *reinterpret_cast<const float4*>(gp + c4 * 4);
            float pr[4] = {v.x + bb.x, v.y + bb.y, v.z + bb.z, v.w + bb.w};
            float hr[4] = {hv.x, hv.y, hv.z, hv.w};
            float gr[4] = {gv.x, gv.y, gv.z, gv.w};
            float4 o;
            float* opv = &o.x;
            #pragma unroll
            for (int j = 0; j < 4; ++j) {
                float alpha = 1.f / (1.f + expf(-pr[j]));
                opv[j] = alpha * hr[j] + (1.f - alpha) * gr[j];
            }
            *reinterpret_cast<float4*>(op + c4 * 4) = o;
        }
    } else if (MODE == 0) {
        int l = m & (L_ - 1);
        bool on = count_of(l) > 0;
        float* gp = d_G + (size_t)m * D_ + nbase;
        #pragma unroll
        for (int c4 = 0; c4 < 16; ++c4) {
            float4 v = *reinterpret_cast<const float4*>(row + c4 * 4);
            float4 bb = *reinterpret_cast<const float4*>(bias + nbase + c4 * 4);
            float4 o;
            o.x = on ? v.x + bb.x : 0.f;
            o.y = on ? v.y + bb.y : 0.f;
            o.z = on ? v.z + bb.z : 0.f;
            o.w = on ? v.w + bb.w : 0.f;
            *reinterpret_cast<float4*>(gp + c4 * 4) = o;
        }
    } else {
        float* up = out + (size_t)m * GEO_ + nbase;
        #pragma unroll
        for (int c4 = 0; c4 < 16; ++c4) {
            float4 v = *reinterpret_cast<const float4*>(row + c4 * 4);
            float4 bb = *reinterpret_cast<const float4*>(bias + nbase + c4 * 4);
            float4 o;
            o.x = gelu_exact(v.x + bb.x);
            o.y = gelu_exact(v.y + bb.y);
            o.z = gelu_exact(v.z + bb.z);
            o.w = gelu_exact(v.w + bb.w);
            *reinterpret_cast<float4*>(up + c4 * 4) = o;
        }
    }
}

extern "C" void kernel_launch(void* const* d_in, const int* in_sizes, int n_in,
                              void* d_out, int out_size) {
    const float* h   = (const float*)d_in[0];
    const float* rw  = (const float*)d_in[1];
    const float* rb  = (const float*)d_in[2];
    const float* g1w = (const float*)d_in[3];
    const float* g1b = (const float*)d_in[4];
    const float* g2w = (const float*)d_in[5];
    const float* g2b = (const float*)d_in[6];
    const float* gw  = (const float*)d_in[7];
    const float* gb  = (const float*)d_in[8];
    float* out = (float*)d_out;
    (void)in_sizes; (void)n_in; (void)out_size;

    cudaFuncSetAttribute(k_gemm<0>, cudaFuncAttributeMaxDynamicSharedMemorySize, SMEM_GEMM);
    cudaFuncSetAttribute(k_gemm<1>, cudaFuncAttributeMaxDynamicSharedMemorySize, SMEM_GEMM);
    cudaFuncSetAttribute(k_gemm<2>, cudaFuncAttributeMaxDynamicSharedMemorySize, SMEM_GEMM);

    float *pP, *pU, *pS, *pG1;
    cudaGetSymbolAddress((void**)&pP, d_P);
    cudaGetSymbolAddress((void**)&pU, d_U);
    cudaGetSymbolAddress((void**)&pS, d_S);
    cudaGetSymbolAddress((void**)&pG1, d_G1p);

    k_pad_g1<<<PLUP_ * GEO_ / 1024, 256>>>(g1w);
    k_z<<<BL_ / 16, 256>>>(h, rw, rb);

    // geometry path
    k_plucker<<<MROWS_ / 8, 256>>>();
    k_gemm<2><<<dim3(GEO_ / 128, MROWS_ / 128), 256, SMEM_GEMM>>>(
        pP, pG1, g1b, pU);
    k_reduce<<<BL_ * GEO_ / 1024, 256>>>();

    // g = S @ g2_w + b -> d_G
    k_gemm<0><<<dim3(D_ / 128, BL_ / 128), 256, SMEM_GEMM>>>(
        pS, g2w, g2b, nullptr);

    // gated output
    k_gemm<1><<<dim3(D_ / 128, BL_ / 128), 256, SMEM_GEMM>>>(
        h, gw, gb, out);
}

// round 10
// speedup vs baseline: 2.5378x; 1.0843x over previous
#include <cuda_runtime.h>
#include <mma.h>
#include <math.h>
#include <stdint.h>

using namespace nvcuda;

#define B_ 4
#define L_ 4096
#define D_ 1024
#define R_ 16
#define PLU_ 120
#define PLUP_ 128
#define GEO_ 256
#define BL_ 16384
#define MROWS_ (6 * BL_)
#define EPS_ 1e-6f

// Scratch (static device globals: allocation-free)
__device__ float d_Z[BL_ * R_];                  // (B*L, 16)
__device__ float d_S[BL_ * GEO_];                // (B*L, 256)
__device__ float d_P[(size_t)MROWS_ * PLUP_];    // plucker rows (cols 120..127 = 0)
__device__ float d_U[(size_t)MROWS_ * GEO_];     // gelu(P@g1w+b)
__device__ float d_G[(size_t)BL_ * D_];          // g (raw fp32)
__device__ float d_G1p[PLUP_ * GEO_];            // g1_w padded to 128 rows

__constant__ int c_off[6] = {1, 2, 4, 8, 16, 32};

__device__ __forceinline__ uint32_t smem_u32(const void* p) {
    uint32_t a;
    asm("{ .reg .u64 t; cvta.to.shared.u64 t, %1; cvt.u32.u64 %0, t; }"
        : "=r"(a) : "l"(p));
    return a;
}
__device__ __forceinline__ void cp16(uint32_t s, const void* g) {
    asm volatile("cp.async.cg.shared.global [%0], [%1], 16;" :: "r"(s), "l"(g));
}
__device__ __forceinline__ void cp_commit() { asm volatile("cp.async.commit_group;"); }
template <int N>
__device__ __forceinline__ void cp_wait() {
    asm volatile("cp.async.wait_group %0;" :: "n"(N));
}
__device__ __forceinline__ float gelu_exact(float x) {
    return 0.5f * x * (1.f + erff(x * 0.7071067811865476f));
}
__device__ __forceinline__ int count_of(int l) {
    return (l >= 1) + (l >= 2) + (l >= 4) + (l >= 8) + (l >= 16) + (l >= 32);
}

// ---------------- z = h @ red_w + red_b ----------------
__global__ void k_z(const float* __restrict__ h,
                    const float* __restrict__ rw,
                    const float* __restrict__ rb) {
    int t = blockIdx.x * 16 + (threadIdx.x >> 4);
    int r = threadIdx.x & 15;
    const float* hrow = h + (size_t)t * D_;
    float acc = rb[r];
    #pragma unroll 4
    for (int d = 0; d < D_; d += 4) {
        float4 hv = *reinterpret_cast<const float4*>(hrow + d);
        acc += hv.x * rw[(d + 0) * R_ + r];
        acc += hv.y * rw[(d + 1) * R_ + r];
        acc += hv.z * rw[(d + 2) * R_ + r];
        acc += hv.w * rw[(d + 3) * R_ + r];
    }
    d_Z[t * R_ + r] = acc;
}

// ---------------- pad g1_w 120 -> 128 rows ----------------
__global__ void k_pad_g1(const float* __restrict__ g1w) {
    int fid = blockIdx.x * 256 + threadIdx.x;   // 8192 float4s
    int row = fid >> 6;
    int c = (fid & 63) * 4;
    float4 v = make_float4(0.f, 0.f, 0.f, 0.f);
    if (row < PLU_)
        v = *reinterpret_cast<const float4*>(g1w + (size_t)row * GEO_ + c);
    *reinterpret_cast<float4*>(d_G1p + (size_t)row * GEO_ + c) = v;
}

// ---------------- plucker rows: d_P[di*BL + t][0:128] ----------------
// All shuffles warp-uniform.
__global__ void k_plucker() {
    int wid = threadIdx.x >> 5, lane = threadIdx.x & 31;
    int ridx = blockIdx.x * 8 + wid;
    int di = ridx / BL_;
    int t = ridx - di * BL_;
    int l = t & (L_ - 1);
    int delta = c_off[di];
    float* dst = d_P + (size_t)ridx * PLUP_;
    if (l < delta) {                       // warp-uniform branch
        #pragma unroll
        for (int q = 0; q < 4; ++q) dst[lane + q * 32] = 0.f;
        return;
    }
    int tp = t - delta;
    float w = (lane < 16) ? d_Z[tp * R_ + lane] : d_Z[t * R_ + lane - 16];
    float p[4];
    float sq = 0.f;
    #pragma unroll
    for (int q = 0; q < 4; ++q) {
        int k = lane + q * 32;
        int kc = (k < PLU_) ? k : 0;
        int kk = kc, i = 0, len = R_ - 1;
        while (kk >= len) { kk -= len; i++; len--; }
        int j = i + 1 + kk;
        float ui = __shfl_sync(0xffffffffu, w, i);
        float uj = __shfl_sync(0xffffffffu, w, j);
        float vi = __shfl_sync(0xffffffffu, w, 16 + i);
        float vj = __shfl_sync(0xffffffffu, w, 16 + j);
        float val = (k < PLU_) ? (ui * vj - uj * vi) : 0.f;
        p[q] = val;
        sq += val * val;
    }
    #pragma unroll
    for (int o = 16; o > 0; o >>= 1) sq += __shfl_xor_sync(0xffffffffu, sq, o);
    float inv = 1.f / fmaxf(sqrtf(sq), EPS_);
    #pragma unroll
    for (int q = 0; q < 4; ++q) dst[lane + q * 32] = p[q] * inv;
}

// ---------------- reduce: d_S = (sum masked d_U slices)/cnt ----------------
__global__ void k_reduce() {
    int fid = blockIdx.x * 256 + threadIdx.x;   // BL*GEO/4 float4s
    int t = fid >> 6;
    int c = (fid & 63) * 4;
    int l = t & (L_ - 1);
    float4 s = make_float4(0.f, 0.f, 0.f, 0.f);
    #pragma unroll
    for (int di = 0; di < 6; ++di) {
        if (l >= c_off[di]) {
            float4 u = *reinterpret_cast<const float4*>(
                d_U + (size_t)(di * BL_ + t) * GEO_ + c);
            s.x += u.x; s.y += u.y; s.z += u.z; s.w += u.w;
        }
    }
    int cnt = count_of(l);
    float sc = cnt > 0 ? 1.f / (float)cnt : 0.f;
    s.x *= sc; s.y *= sc; s.z *= sc; s.w *= sc;
    *reinterpret_cast<float4*>(d_S + (size_t)t * GEO_ + c) = s;
}

// ---------------- wmma tf32 GEMM, 128x128 tile, BK=32, 2-stage, 2 CTAs/SM ------
// HW truncates fp32 -> tf32 inside HMMA; no explicit cvt needed.
// MODE 0: A=d_S (K=256),  B=g2_w:   d_G = cnt>0 ? acc + g2b : 0
// MODE 1: A=[h|d_G] (K=2048), B=gate_w: out = sig(acc+gb)*h + (1-sig)*d_G
// MODE 2: A=d_P (K=128),  B=d_G1p (NG=256): d_U = gelu(acc + g1b)
#define LDA 40
#define LDB 136
#define STAGE_F (128 * LDA + 32 * LDB)     // 5120 + 4352 = 9472 floats
#define SMEM_GEMM (2 * STAGE_F * 4)        // 75776 bytes -> 2 CTAs/SM

template <int MODE>
__global__ void __launch_bounds__(256, 2) k_gemm(const float* __restrict__ hA,
                                                 const float* __restrict__ Bw,
                                                 const float* __restrict__ bias,
                                                 float* __restrict__ out) {
    extern __shared__ __align__(128) float sm[];
    constexpr int KTOT = (MODE == 1) ? 2 * D_ : (MODE == 0 ? GEO_ : PLUP_);
    constexpr int NG = (MODE == 2) ? GEO_ : D_;
    constexpr int NIT = KTOT / 32;

    const int tid = threadIdx.x;
    const int wid = tid >> 5, lane = tid & 31;
    const int wm = wid >> 1, wn = wid & 1;
    const int m0 = blockIdx.y * 128;
    const int n0 = blockIdx.x * 128;
    const uint32_t smb = smem_u32(sm);

    wmma::fragment<wmma::accumulator, 16, 16, 8, float> acc[2][4];
    #pragma unroll
    for (int i = 0; i < 2; ++i)
        #pragma unroll
        for (int j = 0; j < 4; ++j) wmma::fill_fragment(acc[i][j], 0.f);

    auto load_async = [&](int it, int s) {
        const int k0 = it * 32;
        const uint32_t aoff = s * STAGE_F;
        const uint32_t boff = s * STAGE_F + 128 * LDA;
        // A: 128 rows x 32 floats -> 1024 float4, 4 per thread
        #pragma unroll
        for (int p = 0; p < 4; ++p) {
            int idx = tid + p * 256;
            int row = idx >> 3, c4 = idx & 7;
            const float* gp;
            if (MODE == 1)
                gp = (k0 < D_) ? hA + (size_t)(m0 + row) * D_ + k0 + c4 * 4
                               : d_G + (size_t)(m0 + row) * D_ + (k0 - D_) + c4 * 4;
            else if (MODE == 0)
                gp = d_S + (size_t)(m0 + row) * GEO_ + k0 + c4 * 4;
            else
                gp = d_P + (size_t)(m0 + row) * PLUP_ + k0 + c4 * 4;
            cp16(smb + (aoff + row * LDA + c4 * 4) * 4, gp);
        }
        // B: 32 rows x 128 floats -> 1024 float4, 4 per thread
        #pragma unroll
        for (int p = 0; p < 4; ++p) {
            int idx = tid + p * 256;
            int row = idx >> 5, c4 = idx & 31;
            cp16(smb + (boff + row * LDB + c4 * 4) * 4,
                 Bw + (size_t)(k0 + row) * NG + n0 + c4 * 4);
        }
        cp_commit();
    };

    auto compute = [&](int s) {
        const float* As = sm + s * STAGE_F;
        const float* Bs = sm + s * STAGE_F + 128 * LDA;
        #pragma unroll
        for (int ks = 0; ks < 4; ++ks) {
            wmma::fragment<wmma::matrix_a, 16, 16, 8, wmma::precision::tf32,
                           wmma::row_major> a[2];
            wmma::fragment<wmma::matrix_b, 16, 16, 8, wmma::precision::tf32,
                           wmma::row_major> b[4];
            #pragma unroll
            for (int i = 0; i < 2; ++i)
                wmma::load_matrix_sync(a[i], As + (wm * 32 + i * 16) * LDA + ks * 8, LDA);
            #pragma unroll
            for (int j = 0; j < 4; ++j)
                wmma::load_matrix_sync(b[j], Bs + ks * 8 * LDB + wn * 64 + j * 16, LDB);
            #pragma unroll
            for (int i = 0; i < 2; ++i)
                #pragma unroll
                for (int j = 0; j < 4; ++j)
                    wmma::mma_sync(acc[i][j], a[i], b[j], acc[i][j]);
        }
    };

    load_async(0, 0);
    for (int it = 0; it < NIT; ++it) {
        int cur = it & 1;
        if (it + 1 < NIT) {
            load_async(it + 1, 1 - cur);
            cp_wait<1>();
        } else {
            cp_wait<0>();
        }
        __syncthreads();
        compute(cur);
        __syncthreads();
    }

    // Epilogue via smem staging (8 warps x 2048 floats = 64KB <= 75.7KB)
    float* ep = sm + wid * 2048;   // 32 rows x 64 cols per warp
    #pragma unroll
    for (int i = 0; i < 2; ++i)
        #pragma unroll
        for (int j = 0; j < 4; ++j)
            wmma::store_matrix_sync(ep + i * 16 * 64 + j * 16, acc[i][j], 64,
                                    wmma::mem_row_major);
    __syncwarp();

    const int m = m0 + wm * 32 + lane;
    const float* row = ep + lane * 64;
    const int nbase = n0 + wn * 64;

    if (MODE == 1) {
        const float* hp = hA + (size_t)m * D_ + nbase;
        const float* gp = d_G + (size_t)m * D_ + nbase;
        float* op = out + (size_t)m * D_ + nbase;
        #pragma unroll
        for (int c4 = 0; c4 < 16; ++c4) {
            float4 v = *reinterpret_cast<const float4*>(row + c4 * 4);
            float4 bb = *reinterpret_cast<const float4*>(bias + nbase + c4 * 4);
            float4 hv = *reinterpret_cast<const float4*>(hp + c4 * 4);
            float4 gv = *reinterpret_cast<const float4*>(gp + c4 * 4);
            float pr[4] = {v.x + bb.x, v.y + bb.y, v.z + bb.z, v.w + bb.w};
            float hr[4] = {hv.x, hv.y, hv.z, hv.w};
            float gr[4] = {gv.x, gv.y, gv.z, gv.w};
            float4 o;
            float* opv = &o.x;
            #pragma unroll
            for (int j = 0; j < 4; ++j) {
                float alpha = 1.f / (1.f + expf(-pr[j]));
                opv[j] = alpha * hr[j] + (1.f - alpha) * gr[j];
            }
            *reinterpret_cast<float4*>(op + c4 * 4) = o;
        }
    } else if (MODE == 0) {
        int l = m & (L_ - 1);
        bool on = count_of(l) > 0;
        float* gp = d_G + (size_t)m * D_ + nbase;
        #pragma unroll
        for (int c4 = 0; c4 < 16; ++c4) {
            float4 v = *reinterpret_cast<const float4*>(row + c4 * 4);
            float4 bb = *reinterpret_cast<const float4*>(bias + nbase + c4 * 4);
            float4 o;
            o.x = on ? v.x + bb.x : 0.f;
            o.y = on ? v.y + bb.y : 0.f;
            o.z = on ? v.z + bb.z : 0.f;
            o.w = on ? v.w + bb.w : 0.f;
            *reinterpret_cast<float4*>(gp + c4 * 4) = o;
        }
    } else {
        float* up = out + (size_t)m * GEO_ + nbase;
        #pragma unroll
        for (int c4 = 0; c4 < 16; ++c4) {
            float4 v = *reinterpret_cast<const float4*>(row + c4 * 4);
            float4 bb = *reinterpret_cast<const float4*>(bias + nbase + c4 * 4);
            float4 o;
            o.x = gelu_exact(v.x + bb.x);
            o.y = gelu_exact(v.y + bb.y);
            o.z = gelu_exact(v.z + bb.z);
            o.w = gelu_exact(v.w + bb.w);
            *reinterpret_cast<float4*>(up + c4 * 4) = o;
        }
    }
}

extern "C" void kernel_launch(void* const* d_in, const int* in_sizes, int n_in,
                              void* d_out, int out_size) {
    const float* h   = (const float*)d_in[0];
    const float* rw  = (const float*)d_in[1];
    const float* rb  = (const float*)d_in[2];
    const float* g1w = (const float*)d_in[3];
    const float* g1b = (const float*)d_in[4];
    const float* g2w = (const float*)d_in[5];
    const float* g2b = (const float*)d_in[6];
    const float* gw  = (const float*)d_in[7];
    const float* gb  = (const float*)d_in[8];
    float* out = (float*)d_out;
    (void)in_sizes; (void)n_in; (void)out_size;

    cudaFuncSetAttribute(k_gemm<0>, cudaFuncAttributeMaxDynamicSharedMemorySize, SMEM_GEMM);
    cudaFuncSetAttribute(k_gemm<1>, cudaFuncAttributeMaxDynamicSharedMemorySize, SMEM_GEMM);
    cudaFuncSetAttribute(k_gemm<2>, cudaFuncAttributeMaxDynamicSharedMemorySize, SMEM_GEMM);

    float *pP, *pU, *pS, *pG1;
    cudaGetSymbolAddress((void**)&pP, d_P);
    cudaGetSymbolAddress((void**)&pU, d_U);
    cudaGetSymbolAddress((void**)&pS, d_S);
    cudaGetSymbolAddress((void**)&pG1, d_G1p);

    k_pad_g1<<<PLUP_ * GEO_ / 1024, 256>>>(g1w);
    k_z<<<BL_ / 16, 256>>>(h, rw, rb);

    // geometry path
    k_plucker<<<MROWS_ / 8, 256>>>();
    k_gemm<2><<<dim3(GEO_ / 128, MROWS_ / 128), 256, SMEM_GEMM>>>(
        pP, pG1, g1b, pU);
    k_reduce<<<BL_ * GEO_ / 1024, 256>>>();

    // g = S @ g2_w + b -> d_G
    k_gemm<0><<<dim3(D_ / 128, BL_ / 128), 256, SMEM_GEMM>>>(
        pS, g2w, g2b, nullptr);

    // gated output
    k_gemm<1><<<dim3(D_ / 128, BL_ / 128), 256, SMEM_GEMM>>>(
        h, gw, gb, out);
}